// round 3
// baseline (speedup 1.0000x reference)
#include <cuda_runtime.h>

// CorrVolume1_4: corr[b,d,h,w] = sum_c L[b,h,w,c] * R[b,h,w-d,c]
// B=8 H=160 W=320 C=128 D=48. Banded GEMM in (w, u=w-d) space.

#define BB 8
#define HH 160
#define WW 320
#define CC 128
#define DD 48
#define WT 64          // w tile per block
#define RT 112         // R rows per block: u in [w0-48, w0+64)
#define STR 132        // smem row stride (floats): rows shift banks by 4 words
#define SMEM_BYTES ((WT + RT) * STR * 4)

__device__ __forceinline__ void fma2(unsigned long long &acc,
                                     unsigned long long a,
                                     unsigned long long b) {
    // packed fp32x2 FMA: 2 FMAs per lane per instruction (sm_10x FFMA2)
    asm("fma.rn.f32x2 %0, %1, %2, %0;" : "+l"(acc) : "l"(a), "l"(b));
}

extern __shared__ float smem[];

__global__ __launch_bounds__(256, 2)
void corrvol_kernel(const float* __restrict__ L,
                    const float* __restrict__ R,
                    float* __restrict__ out) {
    float* Ls = smem;             // [WT][STR]
    float* Rs = smem + WT * STR;  // [RT][STR]

    const int wx = blockIdx.x;    // 0..4
    const int h  = blockIdx.y;    // 0..159
    const int b  = blockIdx.z;    // 0..7
    const int w0 = wx * WT;
    const int tid = threadIdx.x;

    // ---- load L tile: 64 rows x 128 floats (coalesced float4) ----
    const float* Lg = L + ((size_t)(b * HH + h) * WW + w0) * CC;
    #pragma unroll
    for (int k = 0; k < (WT * CC / 4) / 256; k++) {   // 8 iters
        int idx = tid + k * 256;
        int row = idx >> 5;        // 32 float4 per row
        int col = idx & 31;
        float4 v = *(const float4*)(Lg + (size_t)row * CC + col * 4);
        *(float4*)(Ls + row * STR + col * 4) = v;
    }

    // ---- load R tile: 112 rows (u = w0-48+row), zero-fill u<0 ----
    const float* Rg = R + (size_t)(b * HH + h) * WW * CC;
    #pragma unroll
    for (int k = 0; k < (RT * CC / 4) / 256; k++) {   // 14 iters
        int idx = tid + k * 256;
        int row = idx >> 5;
        int col = idx & 31;
        int u = w0 - 48 + row;
        float4 v = make_float4(0.f, 0.f, 0.f, 0.f);
        if (u >= 0) v = *(const float4*)(Rg + (size_t)u * CC + col * 4);
        *(float4*)(Rs + row * STR + col * 4) = v;
    }
    __syncthreads();

    // ---- compute mapping ----
    // warp = (a: 16-wide w strip, uh: 32-wide u half). lanes: 4 (w) x 8 (u).
    // Thread tile 4x4, strided: w = w0 + 16a + lw + 4i ; u = w0-48 + 16a + 32*uh + lu + 8j
    const int warp = tid >> 5, lane = tid & 31;
    const int a  = warp & 3;
    const int uh = warp >> 2;
    const int lw = lane & 3;
    const int lu = lane >> 2;

    const float* Lp = Ls + (a * 16 + lw) * STR;             // rows += 4*i*STR
    const float* Rp = Rs + (a * 16 + uh * 32 + lu) * STR;   // rows += 8*j*STR (max row 111)

    unsigned long long acc[4][4];
    #pragma unroll
    for (int i = 0; i < 4; i++)
        #pragma unroll
        for (int j = 0; j < 4; j++) acc[i][j] = 0ull;  // (0.0f, 0.0f)

    #pragma unroll 2
    for (int c = 0; c < CC; c += 4) {
        ulonglong2 Lv[4], Rv[4];
        #pragma unroll
        for (int i = 0; i < 4; i++)
            Lv[i] = *(const ulonglong2*)(Lp + 4 * i * STR + c);
        #pragma unroll
        for (int j = 0; j < 4; j++)
            Rv[j] = *(const ulonglong2*)(Rp + 8 * j * STR + c);
        #pragma unroll
        for (int i = 0; i < 4; i++)
            #pragma unroll
            for (int j = 0; j < 4; j++) {
                fma2(acc[i][j], Lv[i].x, Rv[j].x);
                fma2(acc[i][j], Lv[i].y, Rv[j].y);
            }
    }

    // ---- writeout: d = w - u, keep 0 <= d < 48. Each (w,u) pair is covered
    // exactly once across the grid, so every output element is written once. ----
    const int wbase = w0 + a * 16 + lw;
    const int ubase = w0 - 48 + a * 16 + uh * 32 + lu;
    #pragma unroll
    for (int i = 0; i < 4; i++) {
        const int w = wbase + 4 * i;
        #pragma unroll
        for (int j = 0; j < 4; j++) {
            const int u = ubase + 8 * j;
            const int d = w - u;
            if (d >= 0 && d < DD) {
                float2 f = *(float2*)&acc[i][j];
                out[(((size_t)b * DD + d) * HH + h) * WW + w] = f.x + f.y;
            }
        }
    }
}

extern "C" void kernel_launch(void* const* d_in, const int* in_sizes, int n_in,
                              void* d_out, int out_size) {
    const float* L = (const float*)d_in[0];
    const float* R = (const float*)d_in[1];
    float* out = (float*)d_out;

    cudaFuncSetAttribute(corrvol_kernel,
                         cudaFuncAttributeMaxDynamicSharedMemorySize, SMEM_BYTES);

    dim3 grid(WW / WT, HH, BB);   // (5, 160, 8) = 6400 blocks
    corrvol_kernel<<<grid, 256, SMEM_BYTES>>>(L, R, out);
}

// round 4
// speedup vs baseline: 1.0195x; 1.0195x over previous
#include <cuda_runtime.h>

// CorrVolume1_4: corr[b,d,h,w] = sum_c L[b,h,w,c] * R[b,h,w-d,c]
// B=8 H=160 W=320 C=128 D=48. Banded GEMM in (w, u=w-d) space.
// R4: 8x4 thread tile (bytes/FMA 2.0 -> 1.5) to relieve L1TEX (81.6% bound).

#define BB 8
#define HH 160
#define WW 320
#define CC 128
#define DD 48
#define WT 64          // w tile per block
#define RT 112         // R rows per block: u in [w0-48, w0+64)
#define STR 132        // smem row stride (floats): adjacent rows shift banks by 4
#define SMEM_BYTES ((WT + RT) * STR * 4)

__device__ __forceinline__ void fma2(unsigned long long &acc,
                                     unsigned long long a,
                                     unsigned long long b) {
    // packed fp32x2 FMA: 2 FMAs per lane per instruction (sm_10x FFMA2)
    asm("fma.rn.f32x2 %0, %1, %2, %0;" : "+l"(acc) : "l"(a), "l"(b));
}

extern __shared__ float smem[];

__global__ __launch_bounds__(128, 2)
void corrvol_kernel(const float* __restrict__ L,
                    const float* __restrict__ R,
                    float* __restrict__ out) {
    float* Ls = smem;             // [WT][STR]
    float* Rs = smem + WT * STR;  // [RT][STR]

    const int wx = blockIdx.x;    // 0..4
    const int h  = blockIdx.y;    // 0..159
    const int b  = blockIdx.z;    // 0..7
    const int w0 = wx * WT;
    const int tid = threadIdx.x;  // 128 threads

    // ---- load L tile: 64 rows x 128 floats (coalesced float4) ----
    const float* Lg = L + ((size_t)(b * HH + h) * WW + w0) * CC;
    #pragma unroll
    for (int k = 0; k < (WT * CC / 4) / 128; k++) {   // 16 iters
        int idx = tid + k * 128;
        int row = idx >> 5;        // 32 float4 per row
        int col = idx & 31;
        float4 v = *(const float4*)(Lg + (size_t)row * CC + col * 4);
        *(float4*)(Ls + row * STR + col * 4) = v;
    }

    // ---- load R tile: 112 rows (u = w0-48+row), zero-fill u<0 ----
    const float* Rg = R + (size_t)(b * HH + h) * WW * CC;
    #pragma unroll
    for (int k = 0; k < (RT * CC / 4) / 128; k++) {   // 28 iters
        int idx = tid + k * 128;
        int row = idx >> 5;
        int col = idx & 31;
        int u = w0 - 48 + row;
        float4 v = make_float4(0.f, 0.f, 0.f, 0.f);
        if (u >= 0) v = *(const float4*)(Rg + (size_t)u * CC + col * 4);
        *(float4*)(Rs + row * STR + col * 4) = v;
    }
    __syncthreads();

    // ---- compute mapping ----
    // warp a = 16-wide w strip; u window [w0+16a-48, w0+16a+16) (64 wide).
    // lanes: lw (2, in w) x lu (16, in u). Thread tile 8x4, strided:
    //   w = w0 + 16a + lw + 2i   (i = 0..7)
    //   u = w0 + 16a - 48 + lu + 16j  (j = 0..3)  -> rel row 16a + lu + 16j <= 111
    const int warp = tid >> 5, lane = tid & 31;
    const int a  = warp;          // 0..3
    const int lw = lane >> 4;     // 0..1
    const int lu = lane & 15;     // 0..15

    const float* Lp = Ls + (a * 16 + lw) * STR;        // rows += 2*i*STR
    const float* Rp = Rs + (a * 16 + lu) * STR;        // rows += 16*j*STR

    unsigned long long acc[8][4];
    #pragma unroll
    for (int i = 0; i < 8; i++)
        #pragma unroll
        for (int j = 0; j < 4; j++) acc[i][j] = 0ull;  // (0.0f, 0.0f)

    #pragma unroll 2
    for (int c = 0; c < CC; c += 4) {
        ulonglong2 Lv[8], Rv[4];
        #pragma unroll
        for (int j = 0; j < 4; j++)
            Rv[j] = *(const ulonglong2*)(Rp + 16 * j * STR + c);
        #pragma unroll
        for (int i = 0; i < 8; i++)
            Lv[i] = *(const ulonglong2*)(Lp + 2 * i * STR + c);
        #pragma unroll
        for (int i = 0; i < 8; i++)
            #pragma unroll
            for (int j = 0; j < 4; j++) {
                fma2(acc[i][j], Lv[i].x, Rv[j].x);
                fma2(acc[i][j], Lv[i].y, Rv[j].y);
            }
    }

    // ---- writeout: d = w - u, keep 0 <= d < 48. Each (w,u) pair is covered
    // exactly once across the grid, so every output element is written once. ----
    const int wbase = w0 + a * 16 + lw;
    const int ubase = w0 + a * 16 - 48 + lu;
    #pragma unroll
    for (int i = 0; i < 8; i++) {
        const int w = wbase + 2 * i;
        #pragma unroll
        for (int j = 0; j < 4; j++) {
            const int u = ubase + 16 * j;
            const int d = w - u;
            if (d >= 0 && d < DD) {
                float2 f = *(float2*)&acc[i][j];
                out[(((size_t)b * DD + d) * HH + h) * WW + w] = f.x + f.y;
            }
        }
    }
}

extern "C" void kernel_launch(void* const* d_in, const int* in_sizes, int n_in,
                              void* d_out, int out_size) {
    const float* L = (const float*)d_in[0];
    const float* R = (const float*)d_in[1];
    float* out = (float*)d_out;

    cudaFuncSetAttribute(corrvol_kernel,
                         cudaFuncAttributeMaxDynamicSharedMemorySize, SMEM_BYTES);

    dim3 grid(WW / WT, HH, BB);   // (5, 160, 8) = 6400 blocks
    corrvol_kernel<<<grid, 128, SMEM_BYTES>>>(L, R, out);
}

// round 11
// speedup vs baseline: 2.0792x; 2.0394x over previous
#include <cuda_runtime.h>
#include <cuda_fp16.h>
#include <cstdint>

// CorrVolume1_4 via mma.sync.m16n8k16 f16 banded GEMM (no sm_103a-only features).
// corr[b,d,h,w] = sum_c L[b,h,w,c]*R[b,h,w-d,c]; B=8 H=160 W=320 C=128 D=48.
// Block: 64-w tile x 112-u window. Warp = (16-w strip, 32-u half), 16x32x128 GEMM.

#define BB 8
#define HH 160
#define WW 320
#define CC 128
#define DD 48
#define WT 64
#define RT 112
#define LSTR 136                       // smem row stride in halves (128 + 8 pad)
#define SM_L 0
#define SM_R (WT * LSTR * 2)           // 17408
#define SM_BAND (SM_R + RT * LSTR * 2) // 47872
#define BSTR 132
#define SMEM_BYTES (SM_BAND + DD * BSTR * 4)   // 73216

__device__ __forceinline__ uint32_t smem_u32(const void* p) {
    uint32_t a;
    asm("{ .reg .u64 t; cvta.to.shared.u64 t, %1; cvt.u32.u64 %0, t; }" : "=r"(a) : "l"(p));
    return a;
}

extern __shared__ char smem[];

__global__ __launch_bounds__(256)
void corrvol_hmma_kernel(const float* __restrict__ L,
                         const float* __restrict__ R,
                         float* __restrict__ out) {
    const uint32_t smb = smem_u32(smem);
    const int tid  = threadIdx.x;
    const int wid  = tid >> 5, lane = tid & 31;
    const int w0 = blockIdx.x * WT;
    const int h  = blockIdx.y;
    const int b  = blockIdx.z;

    // ---- load + fp16-convert L tile: 64 rows x 128 ----
    const float* Lg = L + ((size_t)(b * HH + h) * WW + w0) * CC;
    #pragma unroll
    for (int i = 0; i < (WT * CC / 4) / 256; i++) {   // 8 iters
        int idx = tid + i * 256;
        int row = idx >> 5;
        int c4  = (idx & 31) * 4;
        float4 v = *(const float4*)(Lg + (size_t)row * CC + c4);
        __half2 h01 = __floats2half2_rn(v.x, v.y);    // x in low half
        __half2 h23 = __floats2half2_rn(v.z, v.w);
        uint2 pk = make_uint2(*(uint32_t*)&h01, *(uint32_t*)&h23);
        *(uint2*)(smem + SM_L + ((size_t)row * LSTR + c4) * 2) = pk;
    }
    // ---- load + convert R window: 112 rows (u = w0-48+row), zero u<0 ----
    const float* Rg = R + (size_t)(b * HH + h) * WW * CC;
    #pragma unroll
    for (int i = 0; i < (RT * CC / 4) / 256; i++) {   // 14 iters
        int idx = tid + i * 256;
        int row = idx >> 5;
        int c4  = (idx & 31) * 4;
        int u = w0 - 48 + row;
        float4 v = make_float4(0.f, 0.f, 0.f, 0.f);
        if (u >= 0) v = *(const float4*)(Rg + (size_t)u * CC + c4);
        __half2 h01 = __floats2half2_rn(v.x, v.y);
        __half2 h23 = __floats2half2_rn(v.z, v.w);
        uint2 pk = make_uint2(*(uint32_t*)&h01, *(uint32_t*)&h23);
        *(uint2*)(smem + SM_R + ((size_t)row * LSTR + c4) * 2) = pk;
    }
    __syncthreads();

    // ---- warp GEMM: warp = (a = wid&3: 16-w strip, uh = wid>>2: 32-u half) ----
    // strip a u-window: rows 16a .. 16a+63 of Rs; warp covers n = uh*32 .. +31.
    const int a  = wid & 3;
    const int uh = wid >> 2;

    // A ldmatrix.x4 per-lane address: matrix = lane>>3 -> {rows 0-7/8-15} x {k0/k+8}
    const int mat = lane >> 3;
    const uint32_t a_addr0 = smb + SM_L +
        (uint32_t)(((a * 16) + ((mat & 1) * 8) + (lane & 7)) * LSTR + ((mat >> 1) * 8)) * 2;
    // B loads: row (n) = 16a + uh*32 + t*8 + lane/4; k offset = 2*(lane&3)
    const char* b_base = smem + SM_R +
        ((size_t)(16 * a + uh * 32 + (lane >> 2)) * LSTR + (lane & 3) * 2) * 2;

    float acc[4][4];
    #pragma unroll
    for (int t = 0; t < 4; t++)
        #pragma unroll
        for (int r = 0; r < 4; r++) acc[t][r] = 0.f;

    #pragma unroll
    for (int k = 0; k < 8; k++) {                 // K = 8 x 16
        uint32_t A0, A1, A2, A3;
        asm volatile("ldmatrix.sync.aligned.m8n8.x4.shared.b16 {%0,%1,%2,%3}, [%4];"
                     : "=r"(A0), "=r"(A1), "=r"(A2), "=r"(A3)
                     : "r"(a_addr0 + (uint32_t)k * 32));
        #pragma unroll
        for (int t = 0; t < 4; t++) {
            const char* bp = b_base + (size_t)t * 8 * LSTR * 2 + k * 32;
            uint32_t B0 = *(const uint32_t*)bp;
            uint32_t B1 = *(const uint32_t*)(bp + 16);
            asm volatile(
                "mma.sync.aligned.m16n8k16.row.col.f32.f16.f16.f32 "
                "{%0,%1,%2,%3}, {%4,%5,%6,%7}, {%8,%9}, {%0,%1,%2,%3};"
                : "+f"(acc[t][0]), "+f"(acc[t][1]), "+f"(acc[t][2]), "+f"(acc[t][3])
                : "r"(A0), "r"(A1), "r"(A2), "r"(A3), "r"(B0), "r"(B1));
        }
    }

    // ---- scatter into band[d][wl]: d = m_in + 48 - n, m_in = lane/4 (+8), wl = 16a+m_in ----
    #pragma unroll
    for (int t = 0; t < 4; t++) {
        #pragma unroll
        for (int r = 0; r < 4; r++) {
            int m_in = (lane >> 2) + ((r >= 2) ? 8 : 0);
            int n    = uh * 32 + t * 8 + 2 * (lane & 3) + (r & 1);
            int d    = m_in + 48 - n;
            if (d >= 0 && d < DD)
                *(float*)(smem + SM_BAND + ((size_t)d * BSTR + a * 16 + m_in) * 4) = acc[t][r];
        }
    }
    __syncthreads();

    // ---- coalesced writeout: out[b,d,h,w0+wl] = band[d][wl] ----
    #pragma unroll
    for (int i = 0; i < 3; i++) {                 // 48*16 float4 / 256 = 3
        int g  = tid + i * 256;
        int d  = g >> 4;
        int wl = (g & 15) * 4;
        float4 v = *(float4*)(smem + SM_BAND + ((size_t)d * BSTR + wl) * 4);
        *(float4*)(out + (((size_t)(b * DD + d) * HH + h) * WW) + w0 + wl) = v;
    }
}

extern "C" void kernel_launch(void* const* d_in, const int* in_sizes, int n_in,
                              void* d_out, int out_size) {
    const float* L = (const float*)d_in[0];
    const float* R = (const float*)d_in[1];
    float* out = (float*)d_out;

    cudaFuncSetAttribute(corrvol_hmma_kernel,
                         cudaFuncAttributeMaxDynamicSharedMemorySize, SMEM_BYTES);

    dim3 grid(WW / WT, HH, BB);   // (5, 160, 8) = 6400 blocks
    corrvol_hmma_kernel<<<grid, 256, SMEM_BYTES>>>(L, R, out);
}

// round 13
// speedup vs baseline: 2.5200x; 1.2120x over previous
#include <cuda_runtime.h>
#include <cuda_fp16.h>
#include <cstdint>

// CorrVolume1_4 via mma.sync.m16n8k16 f16 banded GEMM.
// corr[b,d,h,w] = sum_c L[b,h,w,c]*R[b,h,w-d,c]; B=8 H=160 W=320 C=128 D=48.
// Block: 64-w tile x 112-u window. Warp = (16-w strip, 32-u half), 16x32x128 GEMM.
// R12: band buffer overlaid on dead operand smem -> 47.9KB/CTA -> 4 CTAs/SM.

#define BB 8
#define HH 160
#define WW 320
#define CC 128
#define DD 48
#define WT 64
#define RT 112
#define LSTR 136                       // smem row stride in halves (128 + 8 pad)
#define SM_L 0
#define SM_R (WT * LSTR * 2)           // 17408
#define SM_BAND 0                      // overlays L/R region (dead after MMA loop)
#define BSTR 132
#define SMEM_BYTES (SM_R + RT * LSTR * 2)   // 47872 (band 25344 fits inside)

__device__ __forceinline__ uint32_t smem_u32(const void* p) {
    uint32_t a;
    asm("{ .reg .u64 t; cvta.to.shared.u64 t, %1; cvt.u32.u64 %0, t; }" : "=r"(a) : "l"(p));
    return a;
}

extern __shared__ char smem[];

__global__ __launch_bounds__(256)
void corrvol_hmma_kernel(const float* __restrict__ L,
                         const float* __restrict__ R,
                         float* __restrict__ out) {
    const uint32_t smb = smem_u32(smem);
    const int tid  = threadIdx.x;
    const int wid  = tid >> 5, lane = tid & 31;
    const int w0 = blockIdx.x * WT;
    const int h  = blockIdx.y;
    const int b  = blockIdx.z;

    // ---- load + fp16-convert L tile: 64 rows x 128 ----
    const float* Lg = L + ((size_t)(b * HH + h) * WW + w0) * CC;
    #pragma unroll
    for (int i = 0; i < (WT * CC / 4) / 256; i++) {   // 8 iters
        int idx = tid + i * 256;
        int row = idx >> 5;
        int c4  = (idx & 31) * 4;
        float4 v = *(const float4*)(Lg + (size_t)row * CC + c4);
        __half2 h01 = __floats2half2_rn(v.x, v.y);    // x in low half
        __half2 h23 = __floats2half2_rn(v.z, v.w);
        uint2 pk = make_uint2(*(uint32_t*)&h01, *(uint32_t*)&h23);
        *(uint2*)(smem + SM_L + ((size_t)row * LSTR + c4) * 2) = pk;
    }
    // ---- load + convert R window: 112 rows (u = w0-48+row), zero u<0 ----
    const float* Rg = R + (size_t)(b * HH + h) * WW * CC;
    #pragma unroll
    for (int i = 0; i < (RT * CC / 4) / 256; i++) {   // 14 iters
        int idx = tid + i * 256;
        int row = idx >> 5;
        int c4  = (idx & 31) * 4;
        int u = w0 - 48 + row;
        float4 v = make_float4(0.f, 0.f, 0.f, 0.f);
        if (u >= 0) v = *(const float4*)(Rg + (size_t)u * CC + c4);
        __half2 h01 = __floats2half2_rn(v.x, v.y);
        __half2 h23 = __floats2half2_rn(v.z, v.w);
        uint2 pk = make_uint2(*(uint32_t*)&h01, *(uint32_t*)&h23);
        *(uint2*)(smem + SM_R + ((size_t)row * LSTR + c4) * 2) = pk;
    }
    __syncthreads();

    // ---- warp GEMM: warp = (a = wid&3: 16-w strip, uh = wid>>2: 32-u half) ----
    const int a  = wid & 3;
    const int uh = wid >> 2;

    // A ldmatrix.x4 per-lane address: matrix = lane>>3 -> {rows 0-7/8-15} x {k0/k+8}
    const int mat = lane >> 3;
    const uint32_t a_addr0 = smb + SM_L +
        (uint32_t)(((a * 16) + ((mat & 1) * 8) + (lane & 7)) * LSTR + ((mat >> 1) * 8)) * 2;
    // B loads: row (n) = 16a + uh*32 + t*8 + lane/4; k offset = 2*(lane&3)
    const char* b_base = smem + SM_R +
        ((size_t)(16 * a + uh * 32 + (lane >> 2)) * LSTR + (lane & 3) * 2) * 2;

    float acc[4][4];
    #pragma unroll
    for (int t = 0; t < 4; t++)
        #pragma unroll
        for (int r = 0; r < 4; r++) acc[t][r] = 0.f;

    #pragma unroll
    for (int k = 0; k < 8; k++) {                 // K = 8 x 16
        uint32_t A0, A1, A2, A3;
        asm volatile("ldmatrix.sync.aligned.m8n8.x4.shared.b16 {%0,%1,%2,%3}, [%4];"
                     : "=r"(A0), "=r"(A1), "=r"(A2), "=r"(A3)
                     : "r"(a_addr0 + (uint32_t)k * 32));
        #pragma unroll
        for (int t = 0; t < 4; t++) {
            const char* bp = b_base + (size_t)t * 8 * LSTR * 2 + k * 32;
            uint32_t B0 = *(const uint32_t*)bp;
            uint32_t B1 = *(const uint32_t*)(bp + 16);
            asm volatile(
                "mma.sync.aligned.m16n8k16.row.col.f32.f16.f16.f32 "
                "{%0,%1,%2,%3}, {%4,%5,%6,%7}, {%8,%9}, {%0,%1,%2,%3};"
                : "+f"(acc[t][0]), "+f"(acc[t][1]), "+f"(acc[t][2]), "+f"(acc[t][3])
                : "r"(A0), "r"(A1), "r"(A2), "r"(A3), "r"(B0), "r"(B1));
        }
    }

    // All warps must finish reading L/R before the band overlay is written.
    __syncthreads();

    // ---- scatter into band[d][wl]: d = m_in + 48 - n, m_in = lane/4 (+8), wl = 16a+m_in ----
    #pragma unroll
    for (int t = 0; t < 4; t++) {
        #pragma unroll
        for (int r = 0; r < 4; r++) {
            int m_in = (lane >> 2) + ((r >= 2) ? 8 : 0);
            int n    = uh * 32 + t * 8 + 2 * (lane & 3) + (r & 1);
            int d    = m_in + 48 - n;
            if (d >= 0 && d < DD)
                *(float*)(smem + SM_BAND + ((size_t)d * BSTR + a * 16 + m_in) * 4) = acc[t][r];
        }
    }
    __syncthreads();

    // ---- coalesced writeout: out[b,d,h,w0+wl] = band[d][wl] ----
    #pragma unroll
    for (int i = 0; i < 3; i++) {                 // 48*16 float4 / 256 = 3
        int g  = tid + i * 256;
        int d  = g >> 4;
        int wl = (g & 15) * 4;
        float4 v = *(float4*)(smem + SM_BAND + ((size_t)d * BSTR + wl) * 4);
        *(float4*)(out + (((size_t)(b * DD + d) * HH + h) * WW) + w0 + wl) = v;
    }
}

extern "C" void kernel_launch(void* const* d_in, const int* in_sizes, int n_in,
                              void* d_out, int out_size) {
    const float* L = (const float*)d_in[0];
    const float* R = (const float*)d_in[1];
    float* out = (float*)d_out;

    cudaFuncSetAttribute(corrvol_hmma_kernel,
                         cudaFuncAttributeMaxDynamicSharedMemorySize, SMEM_BYTES);

    dim3 grid(WW / WT, HH, BB);   // (5, 160, 8) = 6400 blocks
    corrvol_hmma_kernel<<<grid, 256, SMEM_BYTES>>>(L, R, out);
}